// round 1
// baseline (speedup 1.0000x reference)
#include <cuda_runtime.h>
#include <math.h>

#define Bsz 2
#define Ssz 1024
#define Dm  768
#define Hn  12
#define HDm 64
#define Ln  12
#define Vv  50304
#define TD  (Bsz*Ssz)   /* 2048 rows */

// ---------------- scratch (no allocation allowed) ----------------
__device__ float g_x  [TD * Dm];        // residual stream
__device__ float g_h  [TD * Dm];        // LN output / generic
__device__ float g_qkv[TD * 3 * Dm];    // qkv projections
__device__ float g_o  [TD * Dm];        // attention output
__device__ float g_mlp[TD * 4 * Dm];    // fc1 activations

// ---------------- embedding ----------------
__global__ void embed_kernel(const int* __restrict__ ids,
                             const float* __restrict__ wte,
                             const float* __restrict__ wpe,
                             float* __restrict__ x) {
    int i = blockIdx.x * blockDim.x + threadIdx.x;
    if (i >= TD * Dm) return;
    int d = i % Dm;
    int t = i / Dm;
    int s = t % Ssz;
    x[i] = wte[(size_t)ids[t] * Dm + d] + wpe[(size_t)s * Dm + d];
}

// ---------------- layernorm (one block per row, 256 threads, D=768) --------
__global__ void ln_kernel(const float* __restrict__ x,
                          const float* __restrict__ g,
                          const float* __restrict__ b,
                          float* __restrict__ y, float eps) {
    int row = blockIdx.x;
    int tid = threadIdx.x;                 // 256
    const float* xr = x + (size_t)row * Dm;
    float v0 = xr[tid], v1 = xr[tid + 256], v2 = xr[tid + 512];

    __shared__ float red[256];
    red[tid] = v0 + v1 + v2;
    __syncthreads();
    for (int o = 128; o > 0; o >>= 1) {
        if (tid < o) red[tid] += red[tid + o];
        __syncthreads();
    }
    float mu = red[0] * (1.0f / Dm);
    __syncthreads();

    float d0 = v0 - mu, d1 = v1 - mu, d2 = v2 - mu;
    red[tid] = d0 * d0 + d1 * d1 + d2 * d2;
    __syncthreads();
    for (int o = 128; o > 0; o >>= 1) {
        if (tid < o) red[tid] += red[tid + o];
        __syncthreads();
    }
    float rstd = rsqrtf(red[0] * (1.0f / Dm) + eps);

    float* yr = y + (size_t)row * Dm;
    yr[tid]       = d0 * rstd * g[tid]       + b[tid];
    yr[tid + 256] = d1 * rstd * g[tid + 256] + b[tid + 256];
    yr[tid + 512] = d2 * rstd * g[tid + 512] + b[tid + 512];
}

// ---------------- SGEMM 128x128x8, 8x8 per thread ----------------
// C[M,N] = A[M,K] @ op(B) + bias[N]  (+gelu | +residual)
// TB==0: B is [K,N] row-major.  TB==1: B is [N,K] row-major (B^T).
// epi: 0 = bias only, 1 = bias+gelu(exact), 2 = bias+residual add
// All of M,N divisible by 128 and K divisible by 8 for every call site.
template <int TB>
__global__ void __launch_bounds__(256)
sgemm_kernel(const float* __restrict__ A, const float* __restrict__ B,
             const float* __restrict__ bias, const float* __restrict__ res,
             float* __restrict__ C, int M, int N, int K, int epi) {
    __shared__ float As[8][128];
    __shared__ float Bs[8][128];

    int tid = threadIdx.x;
    int bx = blockIdx.x, by = blockIdx.y;
    int tx = tid % 16, ty = tid / 16;

    float acc[8][8];
#pragma unroll
    for (int i = 0; i < 8; i++)
#pragma unroll
        for (int j = 0; j < 8; j++) acc[i][j] = 0.0f;

    int aRow = tid >> 1;             // 0..127
    int aCol = (tid & 1) * 4;        // 0 or 4
    const float* Aptr = A + (size_t)(by * 128 + aRow) * K + aCol;

    for (int k0 = 0; k0 < K; k0 += 8) {
        float4 av = *(const float4*)(Aptr + k0);
        As[aCol + 0][aRow] = av.x;
        As[aCol + 1][aRow] = av.y;
        As[aCol + 2][aRow] = av.z;
        As[aCol + 3][aRow] = av.w;

        if (TB == 0) {
            int bRow = tid >> 5;         // 0..7
            int bCol = (tid & 31) * 4;   // 0..124
            float4 bv = *(const float4*)(B + (size_t)(k0 + bRow) * N + bx * 128 + bCol);
            *(float4*)&Bs[bRow][bCol] = bv;
        } else {
            int nIdx = tid >> 1;
            int kI   = (tid & 1) * 4;
            float4 bv = *(const float4*)(B + (size_t)(bx * 128 + nIdx) * K + k0 + kI);
            Bs[kI + 0][nIdx] = bv.x;
            Bs[kI + 1][nIdx] = bv.y;
            Bs[kI + 2][nIdx] = bv.z;
            Bs[kI + 3][nIdx] = bv.w;
        }
        __syncthreads();

#pragma unroll
        for (int kk = 0; kk < 8; kk++) {
            float a_[8], b_[8];
#pragma unroll
            for (int i = 0; i < 8; i++) a_[i] = As[kk][ty * 8 + i];
#pragma unroll
            for (int j = 0; j < 8; j++) b_[j] = Bs[kk][tx * 8 + j];
#pragma unroll
            for (int i = 0; i < 8; i++)
#pragma unroll
                for (int j = 0; j < 8; j++) acc[i][j] += a_[i] * b_[j];
        }
        __syncthreads();
    }

#pragma unroll
    for (int i = 0; i < 8; i++) {
        int m = by * 128 + ty * 8 + i;
#pragma unroll
        for (int j = 0; j < 8; j++) {
            int n = bx * 128 + tx * 8 + j;
            float c = acc[i][j] + bias[n];
            if (epi == 1) {
                c = 0.5f * c * (1.0f + erff(c * 0.70710678118654752f));
            } else if (epi == 2) {
                c += res[(size_t)m * N + n];
            }
            C[(size_t)m * N + n] = c;
        }
    }
}

// ---------------- attention: one block per (q, head, batch) ----------------
// qkv layout: [b, s, h*192 + {q:0..63, k:64..127, v:128..191}]
__global__ void __launch_bounds__(128)
attn_kernel(const float* __restrict__ qkv, const float* __restrict__ amask,
            float* __restrict__ o) {
    int qi = blockIdx.x, h = blockIdx.y, b = blockIdx.z;
    int tid = threadIdx.x;   // 128

    __shared__ float sc[Ssz];
    __shared__ float qs[HDm];
    __shared__ float red[128];

    const float* qrow = qkv + (size_t)(b * Ssz + qi) * (3 * Dm) + h * 3 * HDm;
    if (tid < HDm) qs[tid] = qrow[tid];
    __syncthreads();

    // scores + running max
    float lmax = -1e30f;
    for (int k = tid; k < Ssz; k += 128) {
        float madd = (1.0f - amask[b * Ssz + k]) * -10000.0f;
        float s;
        if (k <= qi) {
            const float* kr = qkv + (size_t)(b * Ssz + k) * (3 * Dm) + h * 3 * HDm + HDm;
            float dot = 0.0f;
#pragma unroll 16
            for (int d = 0; d < HDm; d++) dot += qs[d] * kr[d];
            s = dot * 0.125f + madd;
        } else {
            s = -10000.0f + madd;   // causal-masked, matches reference exactly
        }
        sc[k] = s;
        lmax = fmaxf(lmax, s);
    }
    red[tid] = lmax;
    __syncthreads();
    for (int off = 64; off > 0; off >>= 1) {
        if (tid < off) red[tid] = fmaxf(red[tid], red[tid + off]);
        __syncthreads();
    }
    float mx = red[0];
    __syncthreads();

    // exp + sum
    float lsum = 0.0f;
    for (int k = tid; k < Ssz; k += 128) {
        float e = expf(sc[k] - mx);
        sc[k] = e;
        lsum += e;
    }
    red[tid] = lsum;
    __syncthreads();
    for (int off = 64; off > 0; off >>= 1) {
        if (tid < off) red[tid] += red[tid + off];
        __syncthreads();
    }
    float inv = 1.0f / red[0];
    __syncthreads();

    // P @ V : threads split as (d = tid&63, half = tid>>6); masked keys have p==0
    int d = tid & 63;
    int half = tid >> 6;
    const float* vbase = qkv + (size_t)(b * Ssz) * (3 * Dm) + h * 3 * HDm + 2 * HDm + d;
    float acc = 0.0f;
    int kend = qi + 1;
    for (int k = half; k < kend; k += 2) {
        acc += sc[k] * vbase[(size_t)k * (3 * Dm)];
    }
    red[tid] = acc;
    __syncthreads();
    if (tid < 64) {
        o[(size_t)(b * Ssz + qi) * Dm + h * HDm + d] = (red[tid] + red[tid + 64]) * inv;
    }
}

// ---------------- host orchestration ----------------
extern "C" void kernel_launch(void* const* d_in, const int* in_sizes, int n_in,
                              void* d_out, int out_size) {
    const int*   ids    = (const int*)  d_in[0];
    const float* amask  = (const float*)d_in[1];
    const float* wte    = (const float*)d_in[2];
    const float* wpe    = (const float*)d_in[3];
    const float* ln1_g  = (const float*)d_in[4];
    const float* ln1_b  = (const float*)d_in[5];
    const float* qkv_w  = (const float*)d_in[6];
    const float* qkv_b  = (const float*)d_in[7];
    const float* proj_w = (const float*)d_in[8];
    const float* proj_b = (const float*)d_in[9];
    const float* ln2_g  = (const float*)d_in[10];
    const float* ln2_b  = (const float*)d_in[11];
    const float* fc1_w  = (const float*)d_in[12];
    const float* fc1_b  = (const float*)d_in[13];
    const float* fc2_w  = (const float*)d_in[14];
    const float* fc2_b  = (const float*)d_in[15];
    const float* lnf_g  = (const float*)d_in[16];
    const float* lnf_b  = (const float*)d_in[17];
    const float* head_b = (const float*)d_in[18];
    float* out = (float*)d_out;

    float *x, *h, *qkv, *o, *mlp;
    cudaGetSymbolAddress((void**)&x,   g_x);
    cudaGetSymbolAddress((void**)&h,   g_h);
    cudaGetSymbolAddress((void**)&qkv, g_qkv);
    cudaGetSymbolAddress((void**)&o,   g_o);
    cudaGetSymbolAddress((void**)&mlp, g_mlp);

    embed_kernel<<<(TD * Dm + 255) / 256, 256>>>(ids, wte, wpe, x);

    for (int l = 0; l < Ln; l++) {
        // LN1
        ln_kernel<<<TD, 256>>>(x, ln1_g + l * Dm, ln1_b + l * Dm, h, 1e-6f);
        // QKV: [2048,768] @ [768,2304]
        {
            dim3 g(3 * Dm / 128, TD / 128);
            sgemm_kernel<0><<<g, 256>>>(h, qkv_w + (size_t)l * Dm * 3 * Dm,
                                        qkv_b + (size_t)l * 3 * Dm, nullptr,
                                        qkv, TD, 3 * Dm, Dm, 0);
        }
        // attention
        {
            dim3 g(Ssz, Hn, Bsz);
            attn_kernel<<<g, 128>>>(qkv, amask, o);
        }
        // proj + residual: [2048,768] @ [768,768] + x
        {
            dim3 g(Dm / 128, TD / 128);
            sgemm_kernel<0><<<g, 256>>>(o, proj_w + (size_t)l * Dm * Dm,
                                        proj_b + (size_t)l * Dm, x,
                                        x, TD, Dm, Dm, 2);
        }
        // LN2
        ln_kernel<<<TD, 256>>>(x, ln2_g + l * Dm, ln2_b + l * Dm, h, 1e-6f);
        // FC1 + gelu: [2048,768] @ [768,3072]
        {
            dim3 g(4 * Dm / 128, TD / 128);
            sgemm_kernel<0><<<g, 256>>>(h, fc1_w + (size_t)l * Dm * 4 * Dm,
                                        fc1_b + (size_t)l * 4 * Dm, nullptr,
                                        mlp, TD, 4 * Dm, Dm, 1);
        }
        // FC2 + residual: [2048,3072] @ [3072,768] + x
        {
            dim3 g(Dm / 128, TD / 128);
            sgemm_kernel<0><<<g, 256>>>(mlp, fc2_w + (size_t)l * 4 * Dm * Dm,
                                        fc2_b + (size_t)l * Dm, x,
                                        x, TD, Dm, 4 * Dm, 2);
        }
    }

    // final LN
    ln_kernel<<<TD, 256>>>(x, lnf_g, lnf_b, h, 1e-5f);

    // LM head: [2048,768] @ wte^T[768,50304]  (wte stored [V,D] -> TB=1)
    {
        dim3 g(Vv / 128, TD / 128);
        sgemm_kernel<1><<<g, 256>>>(h, wte, head_b, nullptr,
                                    out, TD, Vv, Dm, 0);
    }
}

// round 3
// speedup vs baseline: 1.3974x; 1.3974x over previous
#include <cuda_runtime.h>
#include <cuda_bf16.h>
#include <math.h>
#include <stdint.h>

#define Bsz 2
#define Ssz 1024
#define Dm  768
#define Hn  12
#define HDm 64
#define Ln  12
#define Vv  50304
#define TD  (Bsz*Ssz)   /* 2048 rows */

// ================= helpers =================
__device__ __forceinline__ uint32_t smem_u32(const void* p) {
    uint32_t a;
    asm("{ .reg .u64 t; cvta.to.shared.u64 t, %1; cvt.u32.u64 %0, t; }" : "=r"(a) : "l"(p));
    return a;
}
#define CP_ASYNC16(s, g) asm volatile("cp.async.cg.shared.global [%0], [%1], 16;" :: "r"(s), "l"(g))
#define CP_COMMIT()      asm volatile("cp.async.commit_group;" ::: "memory")
#define CP_WAIT(n)       asm volatile("cp.async.wait_group %0;" :: "n"(n) : "memory")
#define LDSM4(r0,r1,r2,r3,a) \
    asm volatile("ldmatrix.sync.aligned.m8n8.x4.shared.b16 {%0,%1,%2,%3}, [%4];" \
                 : "=r"(r0),"=r"(r1),"=r"(r2),"=r"(r3) : "r"(a))

__device__ __forceinline__ void mma16816(float* c, const uint32_t* a, const uint32_t* b) {
    asm volatile(
        "mma.sync.aligned.m16n8k16.row.col.f32.bf16.bf16.f32 "
        "{%0,%1,%2,%3},{%4,%5,%6,%7},{%8,%9},{%0,%1,%2,%3};"
        : "+f"(c[0]), "+f"(c[1]), "+f"(c[2]), "+f"(c[3])
        : "r"(a[0]), "r"(a[1]), "r"(a[2]), "r"(a[3]), "r"(b[0]), "r"(b[1]));
}

// ================= scratch =================
__device__ __align__(256) float g_x  [TD * Dm];
__device__ __align__(256) float g_qkv[TD * 3 * Dm];
__device__ __align__(256) __nv_bfloat16 g_h_h[TD * Dm],  g_h_l[TD * Dm];
__device__ __align__(256) __nv_bfloat16 g_o_h[TD * Dm],  g_o_l[TD * Dm];
__device__ __align__(256) __nv_bfloat16 g_m_h[TD * 4 * Dm], g_m_l[TD * 4 * Dm];
__device__ __align__(256) __nv_bfloat16 g_qkvw_h[Ln * 3 * Dm * Dm], g_qkvw_l[Ln * 3 * Dm * Dm];
__device__ __align__(256) __nv_bfloat16 g_projw_h[Ln * Dm * Dm],    g_projw_l[Ln * Dm * Dm];
__device__ __align__(256) __nv_bfloat16 g_fc1w_h[Ln * 4 * Dm * Dm], g_fc1w_l[Ln * 4 * Dm * Dm];
__device__ __align__(256) __nv_bfloat16 g_fc2w_h[Ln * Dm * 4 * Dm], g_fc2w_l[Ln * Dm * 4 * Dm];
__device__ __align__(256) __nv_bfloat16 g_wte_h[(size_t)Vv * Dm],   g_wte_l[(size_t)Vv * Dm];

// ================= embedding =================
__global__ void embed_kernel(const int* __restrict__ ids, const float* __restrict__ wte,
                             const float* __restrict__ wpe, float* __restrict__ x) {
    int i = blockIdx.x * blockDim.x + threadIdx.x;
    if (i >= TD * Dm) return;
    int d = i % Dm, t = i / Dm, s = t % Ssz;
    x[i] = wte[(size_t)ids[t] * Dm + d] + wpe[(size_t)s * Dm + d];
}

// ====== weight transpose+split: [L][K][N] f32 -> [L][N][K] bf16 hi/lo ======
__global__ void wconv_t(const float* __restrict__ w, __nv_bfloat16* __restrict__ hi,
                        __nv_bfloat16* __restrict__ lo, int K, int N) {
    __shared__ float t[32][33];
    int l = blockIdx.z;
    int k0 = blockIdx.y * 32, n0 = blockIdx.x * 32;
    const float* src = w + (size_t)l * K * N;
#pragma unroll
    for (int i = 0; i < 4; i++) {
        int k = k0 + threadIdx.y + i * 8;
        t[threadIdx.y + i * 8][threadIdx.x] = src[(size_t)k * N + n0 + threadIdx.x];
    }
    __syncthreads();
#pragma unroll
    for (int i = 0; i < 4; i++) {
        int n = n0 + threadIdx.y + i * 8;
        float v = t[threadIdx.x][threadIdx.y + i * 8];
        __nv_bfloat16 h = __float2bfloat16(v);
        size_t o = ((size_t)l * N + n) * K + k0 + threadIdx.x;
        hi[o] = h;
        lo[o] = __float2bfloat16(v - __bfloat162float(h));
    }
}

__global__ void conv_plain(const float* __restrict__ w, __nv_bfloat16* __restrict__ hi,
                           __nv_bfloat16* __restrict__ lo, size_t n) {
    size_t i = (size_t)blockIdx.x * blockDim.x + threadIdx.x;
    if (i >= n) return;
    float v = w[i];
    __nv_bfloat16 h = __float2bfloat16(v);
    hi[i] = h;
    lo[i] = __float2bfloat16(v - __bfloat162float(h));
}

// ================= layernorm -> hi/lo bf16 =================
__global__ void ln_kernel(const float* __restrict__ x, const float* __restrict__ g,
                          const float* __restrict__ b, __nv_bfloat16* __restrict__ yh,
                          __nv_bfloat16* __restrict__ yl, float eps) {
    int row = blockIdx.x, tid = threadIdx.x;
    const float* xr = x + (size_t)row * Dm;
    float v0 = xr[tid], v1 = xr[tid + 256], v2 = xr[tid + 512];
    __shared__ float red[256];
    red[tid] = v0 + v1 + v2;
    __syncthreads();
    for (int o = 128; o > 0; o >>= 1) { if (tid < o) red[tid] += red[tid + o]; __syncthreads(); }
    float mu = red[0] * (1.0f / Dm);
    __syncthreads();
    float d0 = v0 - mu, d1 = v1 - mu, d2 = v2 - mu;
    red[tid] = d0 * d0 + d1 * d1 + d2 * d2;
    __syncthreads();
    for (int o = 128; o > 0; o >>= 1) { if (tid < o) red[tid] += red[tid + o]; __syncthreads(); }
    float rstd = rsqrtf(red[0] * (1.0f / Dm) + eps);
    size_t base = (size_t)row * Dm;
#pragma unroll
    for (int j = 0; j < 3; j++) {
        int c = tid + j * 256;
        float v = (j == 0 ? d0 : j == 1 ? d1 : d2) * rstd * g[c] + b[c];
        __nv_bfloat16 h = __float2bfloat16(v);
        yh[base + c] = h;
        yl[base + c] = __float2bfloat16(v - __bfloat162float(h));
    }
}

// ================= attention (fp32 in, hi/lo out) =================
__global__ void __launch_bounds__(128)
attn_kernel(const float* __restrict__ qkv, const float* __restrict__ amask,
            __nv_bfloat16* __restrict__ oh, __nv_bfloat16* __restrict__ ol) {
    int qi = blockIdx.x, h = blockIdx.y, b = blockIdx.z;
    int tid = threadIdx.x;
    __shared__ float sc[Ssz];
    __shared__ float qs[HDm];
    __shared__ float red[128];

    const float* qrow = qkv + (size_t)(b * Ssz + qi) * (3 * Dm) + h * 3 * HDm;
    if (tid < HDm) qs[tid] = qrow[tid];
    __syncthreads();

    float lmax = -1e30f;
    for (int k = tid; k < Ssz; k += 128) {
        float madd = (1.0f - amask[b * Ssz + k]) * -10000.0f;
        float s;
        if (k <= qi) {
            const float* kr = qkv + (size_t)(b * Ssz + k) * (3 * Dm) + h * 3 * HDm + HDm;
            float dot = 0.0f;
#pragma unroll 16
            for (int d = 0; d < HDm; d++) dot += qs[d] * kr[d];
            s = dot * 0.125f + madd;
        } else {
            s = -10000.0f + madd;
        }
        sc[k] = s;
        lmax = fmaxf(lmax, s);
    }
    red[tid] = lmax;
    __syncthreads();
    for (int o = 64; o > 0; o >>= 1) { if (tid < o) red[tid] = fmaxf(red[tid], red[tid + o]); __syncthreads(); }
    float mx = red[0];
    __syncthreads();

    float lsum = 0.0f;
    for (int k = tid; k < Ssz; k += 128) {
        float e = expf(sc[k] - mx);
        sc[k] = e;
        lsum += e;
    }
    red[tid] = lsum;
    __syncthreads();
    for (int o = 64; o > 0; o >>= 1) { if (tid < o) red[tid] += red[tid + o]; __syncthreads(); }
    float inv = 1.0f / red[0];
    __syncthreads();

    int d = tid & 63, half = tid >> 6;
    const float* vbase = qkv + (size_t)(b * Ssz) * (3 * Dm) + h * 3 * HDm + 2 * HDm + d;
    float acc = 0.0f;
    for (int k = half; k < qi + 1; k += 2) acc += sc[k] * vbase[(size_t)k * (3 * Dm)];
    red[tid] = acc;
    __syncthreads();
    if (tid < 64) {
        float v = (red[tid] + red[tid + 64]) * inv;
        size_t idx = (size_t)(b * Ssz + qi) * Dm + h * HDm + d;
        __nv_bfloat16 hh = __float2bfloat16(v);
        oh[idx] = hh;
        ol[idx] = __float2bfloat16(v - __bfloat162float(hh));
    }
}

// ================= bf16x3 mma.sync GEMM =================
// C[M,N] = (Ah+Al)[M,K] @ (Bh+Bl)[N,K]^T + bias
// epi 0: fp32 out | epi 1: gelu -> hi/lo bf16 | epi 2: fp32 out + residual
// CTA 128x128, BK=32, 256 threads (8 warps, 2x4 of 64x32 warp tiles)
// smem: 2 buffers x {Ah,Al,Bh,Bl} 8KB tiles = 64KB
__global__ void __launch_bounds__(256, 2)
gemm_kernel(const __nv_bfloat16* __restrict__ Ah, const __nv_bfloat16* __restrict__ Al,
            const __nv_bfloat16* __restrict__ Bh, const __nv_bfloat16* __restrict__ Bl,
            const float* __restrict__ bias, const float* __restrict__ res,
            float* __restrict__ C, __nv_bfloat16* __restrict__ Ch, __nv_bfloat16* __restrict__ Cl,
            int M, int N, int K, int epi) {
    extern __shared__ char smem[];
    const uint32_t sb = smem_u32(smem);
    const int tid = threadIdx.x;
    const int wid = tid >> 5;
    const int lane = tid & 31;
    const int m0 = blockIdx.y * 128;
    const int n0 = blockIdx.x * 128;
    const int wm = (wid >> 2) * 64;      // warp M offset
    const int wn = (wid & 3) * 32;       // warp N offset

    float acc[4][4][4];
#pragma unroll
    for (int i = 0; i < 4; i++)
#pragma unroll
        for (int j = 0; j < 4; j++)
#pragma unroll
            for (int k = 0; k < 4; k++) acc[i][j][k] = 0.0f;

    // cp.async: each thread copies 2 x 16B per tile (4 tiles)
    const int r0_ = tid >> 2,        c0_ = tid & 3;
    const int r1_ = (tid + 256) >> 2, c1_ = (tid + 256) & 3;
    const uint32_t so0 = r0_ * 64 + ((c0_ ^ ((r0_ >> 1) & 3)) * 16);
    const uint32_t so1 = r1_ * 64 + ((c1_ ^ ((r1_ >> 1) & 3)) * 16);

    const __nv_bfloat16* gA0 = Ah + (size_t)m0 * K;
    const __nv_bfloat16* gA1 = Al + (size_t)m0 * K;
    const __nv_bfloat16* gB0 = Bh + (size_t)n0 * K;
    const __nv_bfloat16* gB1 = Bl + (size_t)n0 * K;

    auto issue = [&](int kc, int buf) {
        uint32_t base = sb + buf * 32768;
        const __nv_bfloat16* gp[4] = { gA0 + kc * 32, gA1 + kc * 32, gB0 + kc * 32, gB1 + kc * 32 };
#pragma unroll
        for (int t = 0; t < 4; t++) {
            uint32_t s = base + t * 8192;
            CP_ASYNC16(s + so0, gp[t] + (size_t)r0_ * K + c0_ * 8);
            CP_ASYNC16(s + so1, gp[t] + (size_t)r1_ * K + c1_ * 8);
        }
        CP_COMMIT();
    };

    auto compute = [&](int buf) {
        uint32_t base = sb + buf * 32768;
#pragma unroll
        for (int ks = 0; ks < 2; ks++) {
            uint32_t bh[8], bl[8];
#pragma unroll
            for (int nt2 = 0; nt2 < 2; nt2++) {
                int rn = wn + nt2 * 16 + (lane & 7) + ((lane >> 4) & 1) * 8;
                int cg = ks * 2 + ((lane >> 3) & 1);
                uint32_t off = rn * 64 + ((cg ^ ((rn >> 1) & 3)) * 16);
                LDSM4(bh[nt2 * 4 + 0], bh[nt2 * 4 + 1], bh[nt2 * 4 + 2], bh[nt2 * 4 + 3],
                      base + 16384 + off);
                LDSM4(bl[nt2 * 4 + 0], bl[nt2 * 4 + 1], bl[nt2 * 4 + 2], bl[nt2 * 4 + 3],
                      base + 24576 + off);
            }
#pragma unroll
            for (int mt = 0; mt < 4; mt++) {
                int rm = wm + mt * 16 + (lane & 15);
                int cg = ks * 2 + (lane >> 4);
                uint32_t off = rm * 64 + ((cg ^ ((rm >> 1) & 3)) * 16);
                uint32_t ah[4], al[4];
                LDSM4(ah[0], ah[1], ah[2], ah[3], base + off);
                LDSM4(al[0], al[1], al[2], al[3], base + 8192 + off);
#pragma unroll
                for (int nt = 0; nt < 4; nt++) {
                    mma16816(acc[mt][nt], ah, &bh[nt * 2]);   // hi*hi
                    mma16816(acc[mt][nt], ah, &bl[nt * 2]);   // hi*lo
                    mma16816(acc[mt][nt], al, &bh[nt * 2]);   // lo*hi
                }
            }
        }
    };

    const int NC = K / 32;
    issue(0, 0);
    for (int cc = 0; cc < NC; cc++) {
        if (cc + 1 < NC) {
            issue(cc + 1, (cc + 1) & 1);
            CP_WAIT(1);
        } else {
            CP_WAIT(0);
        }
        __syncthreads();
        compute(cc & 1);
        __syncthreads();
    }

    // ---- epilogue (from registers) ----
    const int rr = lane >> 2;
    const int cc2 = (lane & 3) * 2;
#pragma unroll
    for (int mt = 0; mt < 4; mt++) {
#pragma unroll
        for (int nt = 0; nt < 4; nt++) {
            int m = m0 + wm + mt * 16 + rr;
            int n = n0 + wn + nt * 8 + cc2;
            float b0v = bias[n], b1v = bias[n + 1];
            float v[4];
            v[0] = acc[mt][nt][0] + b0v;
            v[1] = acc[mt][nt][1] + b1v;
            v[2] = acc[mt][nt][2] + b0v;
            v[3] = acc[mt][nt][3] + b1v;
            int mrow[2] = { m, m + 8 };
            if (epi == 1) {
#pragma unroll
                for (int p = 0; p < 2; p++) {
#pragma unroll
                    for (int q = 0; q < 2; q++) {
                        float g = v[p * 2 + q];
                        g = 0.5f * g * (1.0f + erff(g * 0.70710678118654752f));
                        __nv_bfloat16 h = __float2bfloat16(g);
                        size_t o = (size_t)mrow[p] * N + n + q;
                        Ch[o] = h;
                        Cl[o] = __float2bfloat16(g - __bfloat162float(h));
                    }
                }
            } else if (epi == 2) {
#pragma unroll
                for (int p = 0; p < 2; p++) {
                    size_t o = (size_t)mrow[p] * N + n;
                    float2 rv = *(const float2*)(res + o);
                    float2 w;
                    w.x = v[p * 2 + 0] + rv.x;
                    w.y = v[p * 2 + 1] + rv.y;
                    *(float2*)(C + o) = w;
                }
            } else {
#pragma unroll
                for (int p = 0; p < 2; p++) {
                    size_t o = (size_t)mrow[p] * N + n;
                    float2 w;
                    w.x = v[p * 2 + 0];
                    w.y = v[p * 2 + 1];
                    *(float2*)(C + o) = w;
                }
            }
        }
    }
}

#define GEMM_SMEM 65536

// ================= host orchestration =================
extern "C" void kernel_launch(void* const* d_in, const int* in_sizes, int n_in,
                              void* d_out, int out_size) {
    const int*   ids    = (const int*)  d_in[0];
    const float* amask  = (const float*)d_in[1];
    const float* wte    = (const float*)d_in[2];
    const float* wpe    = (const float*)d_in[3];
    const float* ln1_g  = (const float*)d_in[4];
    const float* ln1_b  = (const float*)d_in[5];
    const float* qkv_w  = (const float*)d_in[6];
    const float* qkv_b  = (const float*)d_in[7];
    const float* proj_w = (const float*)d_in[8];
    const float* proj_b = (const float*)d_in[9];
    const float* ln2_g  = (const float*)d_in[10];
    const float* ln2_b  = (const float*)d_in[11];
    const float* fc1_w  = (const float*)d_in[12];
    const float* fc1_b  = (const float*)d_in[13];
    const float* fc2_w  = (const float*)d_in[14];
    const float* fc2_b  = (const float*)d_in[15];
    const float* lnf_g  = (const float*)d_in[16];
    const float* lnf_b  = (const float*)d_in[17];
    const float* head_b = (const float*)d_in[18];
    float* out = (float*)d_out;

    float *x, *qkv;
    __nv_bfloat16 *hh, *hl, *oh, *ol, *mh, *ml;
    __nv_bfloat16 *qwh, *qwl, *pwh, *pwl, *f1h, *f1l, *f2h, *f2l, *wteh, *wtel;
    cudaGetSymbolAddress((void**)&x,    g_x);
    cudaGetSymbolAddress((void**)&qkv,  g_qkv);
    cudaGetSymbolAddress((void**)&hh,   g_h_h);
    cudaGetSymbolAddress((void**)&hl,   g_h_l);
    cudaGetSymbolAddress((void**)&oh,   g_o_h);
    cudaGetSymbolAddress((void**)&ol,   g_o_l);
    cudaGetSymbolAddress((void**)&mh,   g_m_h);
    cudaGetSymbolAddress((void**)&ml,   g_m_l);
    cudaGetSymbolAddress((void**)&qwh,  g_qkvw_h);
    cudaGetSymbolAddress((void**)&qwl,  g_qkvw_l);
    cudaGetSymbolAddress((void**)&pwh,  g_projw_h);
    cudaGetSymbolAddress((void**)&pwl,  g_projw_l);
    cudaGetSymbolAddress((void**)&f1h,  g_fc1w_h);
    cudaGetSymbolAddress((void**)&f1l,  g_fc1w_l);
    cudaGetSymbolAddress((void**)&f2h,  g_fc2w_h);
    cudaGetSymbolAddress((void**)&f2l,  g_fc2w_l);
    cudaGetSymbolAddress((void**)&wteh, g_wte_h);
    cudaGetSymbolAddress((void**)&wtel, g_wte_l);

    cudaFuncSetAttribute(gemm_kernel, cudaFuncAttributeMaxDynamicSharedMemorySize, GEMM_SMEM);

    // weight conversions
    {
        dim3 blk(32, 8);
        wconv_t<<<dim3(3 * Dm / 32, Dm / 32, Ln), blk>>>(qkv_w,  qwh, qwl, Dm, 3 * Dm);
        wconv_t<<<dim3(Dm / 32,     Dm / 32, Ln), blk>>>(proj_w, pwh, pwl, Dm, Dm);
        wconv_t<<<dim3(4 * Dm / 32, Dm / 32, Ln), blk>>>(fc1_w,  f1h, f1l, Dm, 4 * Dm);
        wconv_t<<<dim3(Dm / 32, 4 * Dm / 32, Ln), blk>>>(fc2_w,  f2h, f2l, 4 * Dm, Dm);
        size_t nw = (size_t)Vv * Dm;
        conv_plain<<<(unsigned)((nw + 255) / 256), 256>>>(wte, wteh, wtel, nw);
    }

    embed_kernel<<<(TD * Dm + 255) / 256, 256>>>(ids, wte, wpe, x);

    for (int l = 0; l < Ln; l++) {
        ln_kernel<<<TD, 256>>>(x, ln1_g + l * Dm, ln1_b + l * Dm, hh, hl, 1e-6f);
        // QKV: [2048,768] x [2304,768]^T -> fp32
        gemm_kernel<<<dim3(3 * Dm / 128, TD / 128), 256, GEMM_SMEM>>>(
            hh, hl, qwh + (size_t)l * 3 * Dm * Dm, qwl + (size_t)l * 3 * Dm * Dm,
            qkv_b + (size_t)l * 3 * Dm, nullptr, qkv, nullptr, nullptr,
            TD, 3 * Dm, Dm, 0);
        attn_kernel<<<dim3(Ssz, Hn, Bsz), 128>>>(qkv, amask, oh, ol);
        // proj + residual -> x
        gemm_kernel<<<dim3(Dm / 128, TD / 128), 256, GEMM_SMEM>>>(
            oh, ol, pwh + (size_t)l * Dm * Dm, pwl + (size_t)l * Dm * Dm,
            proj_b + (size_t)l * Dm, x, x, nullptr, nullptr,
            TD, Dm, Dm, 2);
        ln_kernel<<<TD, 256>>>(x, ln2_g + l * Dm, ln2_b + l * Dm, hh, hl, 1e-6f);
        // fc1 + gelu -> hi/lo
        gemm_kernel<<<dim3(4 * Dm / 128, TD / 128), 256, GEMM_SMEM>>>(
            hh, hl, f1h + (size_t)l * 4 * Dm * Dm, f1l + (size_t)l * 4 * Dm * Dm,
            fc1_b + (size_t)l * 4 * Dm, nullptr, nullptr, mh, ml,
            TD, 4 * Dm, Dm, 1);
        // fc2 + residual -> x
        gemm_kernel<<<dim3(Dm / 128, TD / 128), 256, GEMM_SMEM>>>(
            mh, ml, f2h + (size_t)l * Dm * 4 * Dm, f2l + (size_t)l * Dm * 4 * Dm,
            fc2_b + (size_t)l * Dm, x, x, nullptr, nullptr,
            TD, Dm, 4 * Dm, 2);
    }

    ln_kernel<<<TD, 256>>>(x, lnf_g, lnf_b, hh, hl, 1e-5f);

    // LM head: [2048,768] x [50304,768]^T -> out fp32
    gemm_kernel<<<dim3(Vv / 128, TD / 128), 256, GEMM_SMEM>>>(
        hh, hl, wteh, wtel, head_b, nullptr, out, nullptr, nullptr,
        TD, Vv, Dm, 0);
}

// round 4
// speedup vs baseline: 1.4004x; 1.0022x over previous
#include <cuda_runtime.h>
#include <cuda_bf16.h>
#include <math.h>
#include <stdint.h>

#define Bsz 2
#define Ssz 1024
#define Dm  768
#define Hn  12
#define HDm 64
#define Ln  12
#define Vv  50304
#define TD  (Bsz*Ssz)   /* 2048 rows */

// ================= helpers =================
__device__ __forceinline__ uint32_t smem_u32(const void* p) {
    uint32_t a;
    asm("{ .reg .u64 t; cvta.to.shared.u64 t, %1; cvt.u32.u64 %0, t; }" : "=r"(a) : "l"(p));
    return a;
}
#define CP_ASYNC16(s, g) asm volatile("cp.async.cg.shared.global [%0], [%1], 16;" :: "r"(s), "l"(g))
#define CP_COMMIT()      asm volatile("cp.async.commit_group;" ::: "memory")
#define CP_WAIT(n)       asm volatile("cp.async.wait_group %0;" :: "n"(n) : "memory")
#define LDSM4(r0,r1,r2,r3,a) \
    asm volatile("ldmatrix.sync.aligned.m8n8.x4.shared.b16 {%0,%1,%2,%3}, [%4];" \
                 : "=r"(r0),"=r"(r1),"=r"(r2),"=r"(r3) : "r"(a))

__device__ __forceinline__ void mma16816(float* c, const uint32_t* a, const uint32_t* b) {
    asm volatile(
        "mma.sync.aligned.m16n8k16.row.col.f32.bf16.bf16.f32 "
        "{%0,%1,%2,%3},{%4,%5,%6,%7},{%8,%9},{%0,%1,%2,%3};"
        : "+f"(c[0]), "+f"(c[1]), "+f"(c[2]), "+f"(c[3])
        : "r"(a[0]), "r"(a[1]), "r"(a[2]), "r"(a[3]), "r"(b[0]), "r"(b[1]));
}

// ================= scratch =================
__device__ __align__(256) float g_x  [TD * Dm];
__device__ __align__(256) float g_qkv[TD * 3 * Dm];
__device__ __align__(256) __nv_bfloat16 g_h_h[TD * Dm],  g_h_l[TD * Dm];
__device__ __align__(256) __nv_bfloat16 g_o_h[TD * Dm],  g_o_l[TD * Dm];
__device__ __align__(256) __nv_bfloat16 g_m_h[TD * 4 * Dm], g_m_l[TD * 4 * Dm];
__device__ __align__(256) __nv_bfloat16 g_qkvw_h[Ln * 3 * Dm * Dm], g_qkvw_l[Ln * 3 * Dm * Dm];
__device__ __align__(256) __nv_bfloat16 g_projw_h[Ln * Dm * Dm],    g_projw_l[Ln * Dm * Dm];
__device__ __align__(256) __nv_bfloat16 g_fc1w_h[Ln * 4 * Dm * Dm], g_fc1w_l[Ln * 4 * Dm * Dm];
__device__ __align__(256) __nv_bfloat16 g_fc2w_h[Ln * Dm * 4 * Dm], g_fc2w_l[Ln * Dm * 4 * Dm];
__device__ __align__(256) __nv_bfloat16 g_wte_h[(size_t)Vv * Dm],   g_wte_l[(size_t)Vv * Dm];

// ================= embedding =================
__global__ void embed_kernel(const int* __restrict__ ids, const float* __restrict__ wte,
                             const float* __restrict__ wpe, float* __restrict__ x) {
    int i = blockIdx.x * blockDim.x + threadIdx.x;
    if (i >= TD * Dm) return;
    int d = i % Dm, t = i / Dm, s = t % Ssz;
    x[i] = wte[(size_t)ids[t] * Dm + d] + wpe[(size_t)s * Dm + d];
}

// ====== weight transpose+split: [L][K][N] f32 -> [L][N][K] bf16 hi/lo ======
__global__ void wconv_t(const float* __restrict__ w, __nv_bfloat16* __restrict__ hi,
                        __nv_bfloat16* __restrict__ lo, int K, int N) {
    __shared__ float t[32][33];
    int l = blockIdx.z;
    int k0 = blockIdx.y * 32, n0 = blockIdx.x * 32;
    const float* src = w + (size_t)l * K * N;
#pragma unroll
    for (int i = 0; i < 4; i++) {
        int k = k0 + threadIdx.y + i * 8;
        t[threadIdx.y + i * 8][threadIdx.x] = src[(size_t)k * N + n0 + threadIdx.x];
    }
    __syncthreads();
#pragma unroll
    for (int i = 0; i < 4; i++) {
        int n = n0 + threadIdx.y + i * 8;
        float v = t[threadIdx.x][threadIdx.y + i * 8];
        __nv_bfloat16 h = __float2bfloat16(v);
        size_t o = ((size_t)l * N + n) * K + k0 + threadIdx.x;
        hi[o] = h;
        lo[o] = __float2bfloat16(v - __bfloat162float(h));
    }
}

__global__ void conv_plain(const float* __restrict__ w, __nv_bfloat16* __restrict__ hi,
                           __nv_bfloat16* __restrict__ lo, size_t n) {
    size_t i = (size_t)blockIdx.x * blockDim.x + threadIdx.x;
    if (i >= n) return;
    float v = w[i];
    __nv_bfloat16 h = __float2bfloat16(v);
    hi[i] = h;
    lo[i] = __float2bfloat16(v - __bfloat162float(h));
}

// ================= layernorm -> hi/lo bf16 =================
__global__ void ln_kernel(const float* __restrict__ x, const float* __restrict__ g,
                          const float* __restrict__ b, __nv_bfloat16* __restrict__ yh,
                          __nv_bfloat16* __restrict__ yl, float eps) {
    int row = blockIdx.x, tid = threadIdx.x;
    const float* xr = x + (size_t)row * Dm;
    float v0 = xr[tid], v1 = xr[tid + 256], v2 = xr[tid + 512];
    __shared__ float red[256];
    red[tid] = v0 + v1 + v2;
    __syncthreads();
    for (int o = 128; o > 0; o >>= 1) { if (tid < o) red[tid] += red[tid + o]; __syncthreads(); }
    float mu = red[0] * (1.0f / Dm);
    __syncthreads();
    float d0 = v0 - mu, d1 = v1 - mu, d2 = v2 - mu;
    red[tid] = d0 * d0 + d1 * d1 + d2 * d2;
    __syncthreads();
    for (int o = 128; o > 0; o >>= 1) { if (tid < o) red[tid] += red[tid + o]; __syncthreads(); }
    float rstd = rsqrtf(red[0] * (1.0f / Dm) + eps);
    size_t base = (size_t)row * Dm;
#pragma unroll
    for (int j = 0; j < 3; j++) {
        int c = tid + j * 256;
        float v = (j == 0 ? d0 : j == 1 ? d1 : d2) * rstd * g[c] + b[c];
        __nv_bfloat16 h = __float2bfloat16(v);
        yh[base + c] = h;
        yl[base + c] = __float2bfloat16(v - __bfloat162float(h));
    }
}

// ================= attention (fp32 in, hi/lo out) =================
__global__ void __launch_bounds__(128)
attn_kernel(const float* __restrict__ qkv, const float* __restrict__ amask,
            __nv_bfloat16* __restrict__ oh, __nv_bfloat16* __restrict__ ol) {
    int qi = blockIdx.x, h = blockIdx.y, b = blockIdx.z;
    int tid = threadIdx.x;
    __shared__ float sc[Ssz];
    __shared__ float qs[HDm];
    __shared__ float red[128];

    const float* qrow = qkv + (size_t)(b * Ssz + qi) * (3 * Dm) + h * 3 * HDm;
    if (tid < HDm) qs[tid] = qrow[tid];
    __syncthreads();

    float lmax = -1e30f;
    for (int k = tid; k < Ssz; k += 128) {
        float madd = (1.0f - amask[b * Ssz + k]) * -10000.0f;
        float s;
        if (k <= qi) {
            const float* kr = qkv + (size_t)(b * Ssz + k) * (3 * Dm) + h * 3 * HDm + HDm;
            float dot = 0.0f;
#pragma unroll 16
            for (int d = 0; d < HDm; d++) dot += qs[d] * kr[d];
            s = dot * 0.125f + madd;
        } else {
            s = -10000.0f + madd;
        }
        sc[k] = s;
        lmax = fmaxf(lmax, s);
    }
    red[tid] = lmax;
    __syncthreads();
    for (int o = 64; o > 0; o >>= 1) { if (tid < o) red[tid] = fmaxf(red[tid], red[tid + o]); __syncthreads(); }
    float mx = red[0];
    __syncthreads();

    float lsum = 0.0f;
    for (int k = tid; k < Ssz; k += 128) {
        float e = expf(sc[k] - mx);
        sc[k] = e;
        lsum += e;
    }
    red[tid] = lsum;
    __syncthreads();
    for (int o = 64; o > 0; o >>= 1) { if (tid < o) red[tid] += red[tid + o]; __syncthreads(); }
    float inv = 1.0f / red[0];
    __syncthreads();

    int d = tid & 63, half = tid >> 6;
    const float* vbase = qkv + (size_t)(b * Ssz) * (3 * Dm) + h * 3 * HDm + 2 * HDm + d;
    float acc = 0.0f;
    for (int k = half; k < qi + 1; k += 2) acc += sc[k] * vbase[(size_t)k * (3 * Dm)];
    red[tid] = acc;
    __syncthreads();
    if (tid < 64) {
        float v = (red[tid] + red[tid + 64]) * inv;
        size_t idx = (size_t)(b * Ssz + qi) * Dm + h * HDm + d;
        __nv_bfloat16 hh = __float2bfloat16(v);
        oh[idx] = hh;
        ol[idx] = __float2bfloat16(v - __bfloat162float(hh));
    }
}

// ================= bf16x3 mma.sync GEMM (3-stage, ILP-ordered) =================
// C[M,N] = (Ah+Al)[M,K] @ (Bh+Bl)[N,K]^T + bias
// epi 0: fp32 out | epi 1: gelu -> hi/lo bf16 | epi 2: fp32 out + residual
// CTA 128x128, BK=32, 256 threads (8 warps, 2x4 of 64x32 warp tiles)
// smem: 3 stages x {Ah,Al,Bh,Bl} 8KB tiles = 96KB
// grid: x = M tiles (fast-varying -> CTAs sharing a B tile run together)
#define STAGE_BYTES 32768
#define GEMM_SMEM   (3 * STAGE_BYTES)

__global__ void __launch_bounds__(256, 2)
gemm_kernel(const __nv_bfloat16* __restrict__ Ah, const __nv_bfloat16* __restrict__ Al,
            const __nv_bfloat16* __restrict__ Bh, const __nv_bfloat16* __restrict__ Bl,
            const float* __restrict__ bias, const float* __restrict__ res,
            float* __restrict__ C, __nv_bfloat16* __restrict__ Ch, __nv_bfloat16* __restrict__ Cl,
            int M, int N, int K, int epi) {
    extern __shared__ char smem[];
    const uint32_t sb = smem_u32(smem);
    const int tid = threadIdx.x;
    const int wid = tid >> 5;
    const int lane = tid & 31;
    const int m0 = blockIdx.x * 128;   // x = M tiles
    const int n0 = blockIdx.y * 128;   // y = N tiles
    const int wm = (wid >> 2) * 64;
    const int wn = (wid & 3) * 32;

    float acc[4][4][4];
#pragma unroll
    for (int i = 0; i < 4; i++)
#pragma unroll
        for (int j = 0; j < 4; j++)
#pragma unroll
            for (int k = 0; k < 4; k++) acc[i][j][k] = 0.0f;

    const int r0_ = tid >> 2,         c0_ = tid & 3;
    const int r1_ = (tid + 256) >> 2, c1_ = (tid + 256) & 3;
    const uint32_t so0 = r0_ * 64 + ((c0_ ^ ((r0_ >> 1) & 3)) * 16);
    const uint32_t so1 = r1_ * 64 + ((c1_ ^ ((r1_ >> 1) & 3)) * 16);

    const __nv_bfloat16* gA0 = Ah + (size_t)m0 * K;
    const __nv_bfloat16* gA1 = Al + (size_t)m0 * K;
    const __nv_bfloat16* gB0 = Bh + (size_t)n0 * K;
    const __nv_bfloat16* gB1 = Bl + (size_t)n0 * K;

    auto issue = [&](int kc, int buf) {
        uint32_t base = sb + buf * STAGE_BYTES;
        const __nv_bfloat16* gp[4] = { gA0 + kc * 32, gA1 + kc * 32, gB0 + kc * 32, gB1 + kc * 32 };
#pragma unroll
        for (int t = 0; t < 4; t++) {
            uint32_t s = base + t * 8192;
            CP_ASYNC16(s + so0, gp[t] + (size_t)r0_ * K + c0_ * 8);
            CP_ASYNC16(s + so1, gp[t] + (size_t)r1_ * K + c1_ * 8);
        }
        CP_COMMIT();
    };

    auto compute = [&](int buf) {
        uint32_t base = sb + buf * STAGE_BYTES;
#pragma unroll
        for (int ks = 0; ks < 2; ks++) {
            uint32_t bh[8], bl[8];
#pragma unroll
            for (int nt2 = 0; nt2 < 2; nt2++) {
                int rn = wn + nt2 * 16 + (lane & 7) + ((lane >> 4) & 1) * 8;
                int cg = ks * 2 + ((lane >> 3) & 1);
                uint32_t off = rn * 64 + ((cg ^ ((rn >> 1) & 3)) * 16);
                LDSM4(bh[nt2 * 4 + 0], bh[nt2 * 4 + 1], bh[nt2 * 4 + 2], bh[nt2 * 4 + 3],
                      base + 16384 + off);
                LDSM4(bl[nt2 * 4 + 0], bl[nt2 * 4 + 1], bl[nt2 * 4 + 2], bl[nt2 * 4 + 3],
                      base + 24576 + off);
            }
#pragma unroll
            for (int mt = 0; mt < 4; mt++) {
                int rm = wm + mt * 16 + (lane & 15);
                int cg = ks * 2 + (lane >> 4);
                uint32_t off = rm * 64 + ((cg ^ ((rm >> 1) & 3)) * 16);
                uint32_t ah[4], al[4];
                LDSM4(ah[0], ah[1], ah[2], ah[3], base + off);
                LDSM4(al[0], al[1], al[2], al[3], base + 8192 + off);
                // pass-major issue: consecutive mma hit different accumulators (RAW dist 4)
#pragma unroll
                for (int nt = 0; nt < 4; nt++) mma16816(acc[mt][nt], ah, &bh[nt * 2]);
#pragma unroll
                for (int nt = 0; nt < 4; nt++) mma16816(acc[mt][nt], ah, &bl[nt * 2]);
#pragma unroll
                for (int nt = 0; nt < 4; nt++) mma16816(acc[mt][nt], al, &bh[nt * 2]);
            }
        }
    };

    const int NC = K / 32;
    // prologue: 2 chunks in flight
    issue(0, 0);
    issue(1, 1);
    int ibuf = 2;   // buffer for next issue
    int cbuf = 0;   // buffer for compute
    for (int cc = 0; cc < NC; cc++) {
        if (cc + 1 < NC) { CP_WAIT(1); } else { CP_WAIT(0); }
        __syncthreads();
        if (cc + 2 < NC) {
            issue(cc + 2, ibuf);
            ibuf = (ibuf == 2) ? 0 : ibuf + 1;
        }
        compute(cbuf);
        cbuf = (cbuf == 2) ? 0 : cbuf + 1;
    }

    // ---- epilogue (from registers) ----
    const int rr = lane >> 2;
    const int cc2 = (lane & 3) * 2;
#pragma unroll
    for (int mt = 0; mt < 4; mt++) {
#pragma unroll
        for (int nt = 0; nt < 4; nt++) {
            int m = m0 + wm + mt * 16 + rr;
            int n = n0 + wn + nt * 8 + cc2;
            float b0v = bias[n], b1v = bias[n + 1];
            float v[4];
            v[0] = acc[mt][nt][0] + b0v;
            v[1] = acc[mt][nt][1] + b1v;
            v[2] = acc[mt][nt][2] + b0v;
            v[3] = acc[mt][nt][3] + b1v;
            int mrow[2] = { m, m + 8 };
            if (epi == 1) {
#pragma unroll
                for (int p = 0; p < 2; p++) {
#pragma unroll
                    for (int q = 0; q < 2; q++) {
                        float g = v[p * 2 + q];
                        g = 0.5f * g * (1.0f + erff(g * 0.70710678118654752f));
                        __nv_bfloat16 h = __float2bfloat16(g);
                        size_t o = (size_t)mrow[p] * N + n + q;
                        Ch[o] = h;
                        Cl[o] = __float2bfloat16(g - __bfloat162float(h));
                    }
                }
            } else if (epi == 2) {
#pragma unroll
                for (int p = 0; p < 2; p++) {
                    size_t o = (size_t)mrow[p] * N + n;
                    float2 rv = *(const float2*)(res + o);
                    float2 w;
                    w.x = v[p * 2 + 0] + rv.x;
                    w.y = v[p * 2 + 1] + rv.y;
                    *(float2*)(C + o) = w;
                }
            } else {
#pragma unroll
                for (int p = 0; p < 2; p++) {
                    size_t o = (size_t)mrow[p] * N + n;
                    float2 w;
                    w.x = v[p * 2 + 0];
                    w.y = v[p * 2 + 1];
                    *(float2*)(C + o) = w;
                }
            }
        }
    }
}

// ================= host orchestration =================
extern "C" void kernel_launch(void* const* d_in, const int* in_sizes, int n_in,
                              void* d_out, int out_size) {
    const int*   ids    = (const int*)  d_in[0];
    const float* amask  = (const float*)d_in[1];
    const float* wte    = (const float*)d_in[2];
    const float* wpe    = (const float*)d_in[3];
    const float* ln1_g  = (const float*)d_in[4];
    const float* ln1_b  = (const float*)d_in[5];
    const float* qkv_w  = (const float*)d_in[6];
    const float* qkv_b  = (const float*)d_in[7];
    const float* proj_w = (const float*)d_in[8];
    const float* proj_b = (const float*)d_in[9];
    const float* ln2_g  = (const float*)d_in[10];
    const float* ln2_b  = (const float*)d_in[11];
    const float* fc1_w  = (const float*)d_in[12];
    const float* fc1_b  = (const float*)d_in[13];
    const float* fc2_w  = (const float*)d_in[14];
    const float* fc2_b  = (const float*)d_in[15];
    const float* lnf_g  = (const float*)d_in[16];
    const float* lnf_b  = (const float*)d_in[17];
    const float* head_b = (const float*)d_in[18];
    float* out = (float*)d_out;

    float *x, *qkv;
    __nv_bfloat16 *hh, *hl, *oh, *ol, *mh, *ml;
    __nv_bfloat16 *qwh, *qwl, *pwh, *pwl, *f1h, *f1l, *f2h, *f2l, *wteh, *wtel;
    cudaGetSymbolAddress((void**)&x,    g_x);
    cudaGetSymbolAddress((void**)&qkv,  g_qkv);
    cudaGetSymbolAddress((void**)&hh,   g_h_h);
    cudaGetSymbolAddress((void**)&hl,   g_h_l);
    cudaGetSymbolAddress((void**)&oh,   g_o_h);
    cudaGetSymbolAddress((void**)&ol,   g_o_l);
    cudaGetSymbolAddress((void**)&mh,   g_m_h);
    cudaGetSymbolAddress((void**)&ml,   g_m_l);
    cudaGetSymbolAddress((void**)&qwh,  g_qkvw_h);
    cudaGetSymbolAddress((void**)&qwl,  g_qkvw_l);
    cudaGetSymbolAddress((void**)&pwh,  g_projw_h);
    cudaGetSymbolAddress((void**)&pwl,  g_projw_l);
    cudaGetSymbolAddress((void**)&f1h,  g_fc1w_h);
    cudaGetSymbolAddress((void**)&f1l,  g_fc1w_l);
    cudaGetSymbolAddress((void**)&f2h,  g_fc2w_h);
    cudaGetSymbolAddress((void**)&f2l,  g_fc2w_l);
    cudaGetSymbolAddress((void**)&wteh, g_wte_h);
    cudaGetSymbolAddress((void**)&wtel, g_wte_l);

    cudaFuncSetAttribute(gemm_kernel, cudaFuncAttributeMaxDynamicSharedMemorySize, GEMM_SMEM);

    // weight conversions
    {
        dim3 blk(32, 8);
        wconv_t<<<dim3(3 * Dm / 32, Dm / 32, Ln), blk>>>(qkv_w,  qwh, qwl, Dm, 3 * Dm);
        wconv_t<<<dim3(Dm / 32,     Dm / 32, Ln), blk>>>(proj_w, pwh, pwl, Dm, Dm);
        wconv_t<<<dim3(4 * Dm / 32, Dm / 32, Ln), blk>>>(fc1_w,  f1h, f1l, Dm, 4 * Dm);
        wconv_t<<<dim3(Dm / 32, 4 * Dm / 32, Ln), blk>>>(fc2_w,  f2h, f2l, 4 * Dm, Dm);
        size_t nw = (size_t)Vv * Dm;
        conv_plain<<<(unsigned)((nw + 255) / 256), 256>>>(wte, wteh, wtel, nw);
    }

    embed_kernel<<<(TD * Dm + 255) / 256, 256>>>(ids, wte, wpe, x);

    for (int l = 0; l < Ln; l++) {
        ln_kernel<<<TD, 256>>>(x, ln1_g + l * Dm, ln1_b + l * Dm, hh, hl, 1e-6f);
        // QKV: [2048,768] x [2304,768]^T -> fp32    grid(x=M,y=N)
        gemm_kernel<<<dim3(TD / 128, 3 * Dm / 128), 256, GEMM_SMEM>>>(
            hh, hl, qwh + (size_t)l * 3 * Dm * Dm, qwl + (size_t)l * 3 * Dm * Dm,
            qkv_b + (size_t)l * 3 * Dm, nullptr, qkv, nullptr, nullptr,
            TD, 3 * Dm, Dm, 0);
        attn_kernel<<<dim3(Ssz, Hn, Bsz), 128>>>(qkv, amask, oh, ol);
        // proj + residual -> x
        gemm_kernel<<<dim3(TD / 128, Dm / 128), 256, GEMM_SMEM>>>(
            oh, ol, pwh + (size_t)l * Dm * Dm, pwl + (size_t)l * Dm * Dm,
            proj_b + (size_t)l * Dm, x, x, nullptr, nullptr,
            TD, Dm, Dm, 2);
        ln_kernel<<<TD, 256>>>(x, ln2_g + l * Dm, ln2_b + l * Dm, hh, hl, 1e-6f);
        // fc1 + gelu -> hi/lo
        gemm_kernel<<<dim3(TD / 128, 4 * Dm / 128), 256, GEMM_SMEM>>>(
            hh, hl, f1h + (size_t)l * 4 * Dm * Dm, f1l + (size_t)l * 4 * Dm * Dm,
            fc1_b + (size_t)l * 4 * Dm, nullptr, nullptr, mh, ml,
            TD, 4 * Dm, Dm, 1);
        // fc2 + residual -> x
        gemm_kernel<<<dim3(TD / 128, Dm / 128), 256, GEMM_SMEM>>>(
            mh, ml, f2h + (size_t)l * Dm * 4 * Dm, f2l + (size_t)l * Dm * 4 * Dm,
            fc2_b + (size_t)l * Dm, x, x, nullptr, nullptr,
            TD, Dm, 4 * Dm, 2);
    }

    ln_kernel<<<TD, 256>>>(x, lnf_g, lnf_b, hh, hl, 1e-5f);

    // LM head: [2048,768] x [50304,768]^T -> out fp32
    gemm_kernel<<<dim3(TD / 128, Vv / 128), 256, GEMM_SMEM>>>(
        hh, hl, wteh, wtel, head_b, nullptr, out, nullptr, nullptr,
        TD, Vv, Dm, 0);
}